// round 12
// baseline (speedup 1.0000x reference)
#include <cuda_runtime.h>
#include <cuda_fp16.h>
#include <math.h>

#define NN 4096
#define DD 64
#define BIGF 1e30f
#define NWARP 64           // 64 strips of 64 columns, 1 warp each
#define TSTEPS 4128        // 4096 + 32 (lane skew); 129 chunks of 32
#define FULLM 0xffffffffu

// Diagonal-major cost storage: g_costd[((w*TSTEPS)+ss)*32 + lane] holds the
// half2 cost (c[r][c0], c[r][c0+1]) for r = ss - lane, c0 = w*64 + 2*lane.
__device__ __half2 g_costd[(size_t)NWARP * TSTEPS * 32];   // ~33.8 MB
__device__ float  g_nx[NN];
__device__ float  g_ny[NN];
__device__ float  g_c00;                     // c[0][0] for the virtual corner
__device__ float  g_bnd[NWARP * NN];         // right-column boundary per strip
__device__ int    g_flag[NWARP];             // rows completed per strip

// predicated single store — avoids BSSY/BSYNC divergence envelope
__device__ __forceinline__ void st_pred(float* p, float v, int pred) {
    asm volatile("{ .reg .pred p0; setp.ne.s32 p0, %2, 0; @p0 st.global.f32 [%0], %1; }"
                 :: "l"(p), "f"(v), "r"(pred) : "memory");
}

// ---------------------------------------------------------------------------
__global__ void reset_kernel() {
    if (threadIdx.x < NWARP) g_flag[threadIdx.x] = 0;
}

// ---------------------------------------------------------------------------
__global__ void norms_kernel(const float* __restrict__ x, const float* __restrict__ y) {
    int i = blockIdx.x * blockDim.x + threadIdx.x;
    if (i < NN) {
        const float* p = x + (size_t)i * DD;
        float s = 0.f;
        #pragma unroll
        for (int k = 0; k < DD; k++) s += p[k] * p[k];
        g_nx[i] = s;
    } else if (i < 2 * NN) {
        int j = i - NN;
        const float* p = y + (size_t)j * DD;
        float s = 0.f;
        #pragma unroll
        for (int k = 0; k < DD; k++) s += p[k] * p[k];
        g_ny[j] = s;
    }
}

// ---------------------------------------------------------------------------
// Cost matrix: 64x64 tile per block (tile == strip width), 64 threads,
// 8x8 per thread. Results written directly in diagonal-major layout.
// ---------------------------------------------------------------------------
__global__ void __launch_bounds__(64) cost_kernel(const float* __restrict__ x,
                                                  const float* __restrict__ y) {
    __shared__ float xs[64][65];
    __shared__ float ys[64][65];

    const int I0 = blockIdx.y * 64;
    const int w  = blockIdx.x;          // strip id == column tile id
    const int J0 = w * 64;
    const int tid = threadIdx.x;        // 0..63

    #pragma unroll 4
    for (int it = 0; it < 16; it++) {               // 16*64 float4 = 4096 floats
        int idx = (it * 64 + tid) * 4;
        int r = idx >> 6, k = idx & 63;
        float4 vx = *(const float4*)(x + (size_t)(I0 + r) * DD + k);
        float4 vy = *(const float4*)(y + (size_t)(J0 + r) * DD + k);
        xs[r][k] = vx.x; xs[r][k+1] = vx.y; xs[r][k+2] = vx.z; xs[r][k+3] = vx.w;
        ys[r][k] = vy.x; ys[r][k+1] = vy.y; ys[r][k+2] = vy.z; ys[r][k+3] = vy.w;
    }
    __syncthreads();

    const int tx = tid & 7, ty = tid >> 3;
    const int r0 = ty * 8, c0 = tx * 8;

    float acc[8][8];
    #pragma unroll
    for (int a = 0; a < 8; a++)
        #pragma unroll
        for (int b = 0; b < 8; b++) acc[a][b] = 0.f;

    #pragma unroll 4
    for (int k = 0; k < DD; k++) {
        float ra[8], rb[8];
        #pragma unroll
        for (int a = 0; a < 8; a++) ra[a] = xs[r0 + a][k];
        #pragma unroll
        for (int b = 0; b < 8; b++) rb[b] = ys[c0 + b][k];
        #pragma unroll
        for (int a = 0; a < 8; a++)
            #pragma unroll
            for (int b = 0; b < 8; b++) acc[a][b] = fmaf(ra[a], rb[b], acc[a][b]);
    }

    float nyv[8];
    #pragma unroll
    for (int b = 0; b < 8; b++) nyv[b] = g_ny[J0 + c0 + b];

    #pragma unroll
    for (int a = 0; a < 8; a++) {
        const int i = I0 + r0 + a;
        float nx = g_nx[i];
        #pragma unroll
        for (int b2 = 0; b2 < 4; b2++) {
            float s0 = nx + nyv[2*b2]   - 2.0f * acc[a][2*b2];
            float s1 = nx + nyv[2*b2+1] - 2.0f * acc[a][2*b2+1];
            float e0 = sqrtf(fmaxf(s0, 1e-12f));
            float e1 = sqrtf(fmaxf(s1, 1e-12f));
            const int lane = tx * 4 + b2;          // lane owning these 2 cols
            const int ss = i + lane;               // diagonal step index
            g_costd[((size_t)w * TSTEPS + ss) * 32 + lane] = __floats2half2_rn(e0, e1);
        }
    }

    if (w == 0 && I0 == 0 && tid == 0) {
        float sq = g_nx[0] + g_ny[0] - 2.0f * acc[0][0];   // tid0 owns (0,0)
        g_c00 = sqrtf(fmaxf(sq, 1e-12f));
    }
}

// ---------------------------------------------------------------------------
// Persistent DTW: 64 strips x 1 warp; lane owns 2 adjacent columns; at step
// ss computes row r = ss - lane. ONE shfl per step (left value); the diag
// value is the previous step's left value (register rotate); the boundary
// chunk is held in a per-lane register array (broadcast volatile loads once
// per 32-step chunk).
// ---------------------------------------------------------------------------
__global__ void __launch_bounds__(32, 1) dtw_kernel(float* __restrict__ out) {
    const int w = blockIdx.x;
    const int lane = threadIdx.x;
    const __half2* cptr = g_costd + (size_t)w * TSTEPS * 32;

    // state: v1c0/v1c1 = D[prev row][c0/c1]; dg = lfv of previous step
    float v1c0 = BIGF, v1c1 = BIGF, dg = BIGF;
    if (w == 0 && lane == 0)
        dg = -g_c00;                          // virtual corner seed

    float* bndW = g_bnd + (size_t)w * NN;
    const volatile float* bndp = g_bnd + (size_t)(w > 0 ? w - 1 : 0) * NN;
    const volatile int* vflag = (const volatile int*)&g_flag[w > 0 ? w - 1 : 0];
    int* flagW = &g_flag[w];

    // cost prefetch ring (8 steps ahead), coalesced
    __half2 cp[8];
    #pragma unroll
    for (int k = 0; k < 8; k++)
        cp[k] = cptr[(size_t)k * 32 + lane];

    const bool l0 = (lane == 0);

    for (int cs = 0; cs < TSTEPS; cs += 32) {
        // chunk poll + boundary load into registers (uniform branch, 1/32 steps)
        // every lane loads all 32 rows (same-address broadcast loads)
        float bq[32];
        if (w > 0 && cs < NN) {
            while (*vflag < cs + 32) { }
            #pragma unroll
            for (int k = 0; k < 32; k++) bq[k] = bndp[cs + k];
        } else {
            #pragma unroll
            for (int k = 0; k < 32; k++) bq[k] = BIGF;
        }

        #pragma unroll
        for (int k = 0; k < 32; k++) {
            const int ss = cs + k;
            const int r = ss - lane;

            float lfs = __shfl_up_sync(FULLM, v1c1, 1);
            float lfv = l0 ? bq[k] : lfs;

            float2 cc = __half22float2(cp[k & 7]);

            // prefetch cost for step ss+8 (coalesced, off the dependency chain)
            int sl = ss + 8; sl = sl < TSTEPS ? sl : TSTEPS - 1;
            __half2 nxt = cptr[(size_t)sl * 32 + lane];

            float n0 = fminf(fminf(fmaf(2.f, cc.x, dg),   v1c0 + cc.x), lfv + cc.x);
            float n1 = fminf(fminf(fmaf(2.f, cc.y, v1c0), v1c1 + cc.y), n0 + cc.y);

            const bool act = ((unsigned)r < NN);
            v1c0 = act ? n0 : v1c0;
            v1c1 = act ? n1 : v1c1;
            dg = lfv;                                   // diag for step ss+1

            // boundary store (lane31 only, in-range) — predicated, no branch
            int rcl = r < 0 ? 0 : (r > NN - 1 ? NN - 1 : r);
            st_pred(bndW + rcl, n1, (int)(act && lane == 31));

            cp[k & 7] = nxt;
        }

        // publish: flag = cs+1 (lane31 has completed rows 0..cs)
        if (lane == 31) {
            __threadfence();
            atomicExch(flagW, cs + 1);
        }
    }

    if (w == NWARP - 1 && lane == 31)
        out[0] = v1c1;          // D[4095][4095]
}

// ---------------------------------------------------------------------------
extern "C" void kernel_launch(void* const* d_in, const int* in_sizes, int n_in,
                              void* d_out, int out_size) {
    const float* x = (const float*)d_in[0];
    const float* y = (const float*)d_in[1];
    float* out = (float*)d_out;

    reset_kernel<<<1, 64>>>();
    norms_kernel<<<(2 * NN + 511) / 512, 512>>>(x, y);
    cost_kernel<<<dim3(NN / 64, NN / 64), 64>>>(x, y);
    dtw_kernel<<<NWARP, 32>>>(out);
}

// round 13
// speedup vs baseline: 1.8340x; 1.8340x over previous
#include <cuda_runtime.h>
#include <cuda_fp16.h>
#include <math.h>

#define NN 4096
#define DD 64
#define BIGF 1e30f
#define NWARP 64           // 64 strips of 64 columns, 1 warp each
#define TSTEPS 4128        // 4096 + 32 (lane skew); 129 chunks of 32
#define FULLM 0xffffffffu

// Diagonal-major cost storage: g_costd[((w*TSTEPS)+ss)*32 + lane] holds the
// half2 cost (c[r][c0], c[r][c0+1]) for r = ss - lane, c0 = w*64 + 2*lane.
__device__ __half2 g_costd[(size_t)NWARP * TSTEPS * 32];   // ~33.8 MB
__device__ float  g_nx[NN];
__device__ float  g_ny[NN];
__device__ float  g_c00;                     // c[0][0] for the virtual corner
__device__ float  g_bnd[NWARP * NN];         // right-column boundary per strip
__device__ int    g_flag[NWARP];             // rows completed per strip

// predicated single store — no BSSY/BSYNC, no compiler memory barrier
__device__ __forceinline__ void st_pred(float* p, float v, int pred) {
    asm volatile("{ .reg .pred p0; setp.ne.s32 p0, %2, 0; @p0 st.global.f32 [%0], %1; }"
                 :: "l"(p), "f"(v), "r"(pred));
}

// ---------------------------------------------------------------------------
__global__ void reset_kernel() {
    if (threadIdx.x < NWARP) g_flag[threadIdx.x] = 0;
}

// ---------------------------------------------------------------------------
__global__ void norms_kernel(const float* __restrict__ x, const float* __restrict__ y) {
    int i = blockIdx.x * blockDim.x + threadIdx.x;
    if (i < NN) {
        const float* p = x + (size_t)i * DD;
        float s = 0.f;
        #pragma unroll
        for (int k = 0; k < DD; k++) s += p[k] * p[k];
        g_nx[i] = s;
    } else if (i < 2 * NN) {
        int j = i - NN;
        const float* p = y + (size_t)j * DD;
        float s = 0.f;
        #pragma unroll
        for (int k = 0; k < DD; k++) s += p[k] * p[k];
        g_ny[j] = s;
    }
}

// ---------------------------------------------------------------------------
// Cost matrix: 64x64 tile per block (tile == strip width), 64 threads,
// 8x8 per thread. Results written directly in diagonal-major layout.
// ---------------------------------------------------------------------------
__global__ void __launch_bounds__(64) cost_kernel(const float* __restrict__ x,
                                                  const float* __restrict__ y) {
    __shared__ float xs[64][65];
    __shared__ float ys[64][65];

    const int I0 = blockIdx.y * 64;
    const int w  = blockIdx.x;          // strip id == column tile id
    const int J0 = w * 64;
    const int tid = threadIdx.x;        // 0..63

    #pragma unroll 4
    for (int it = 0; it < 16; it++) {               // 16*64 float4 = 4096 floats
        int idx = (it * 64 + tid) * 4;
        int r = idx >> 6, k = idx & 63;
        float4 vx = *(const float4*)(x + (size_t)(I0 + r) * DD + k);
        float4 vy = *(const float4*)(y + (size_t)(J0 + r) * DD + k);
        xs[r][k] = vx.x; xs[r][k+1] = vx.y; xs[r][k+2] = vx.z; xs[r][k+3] = vx.w;
        ys[r][k] = vy.x; ys[r][k+1] = vy.y; ys[r][k+2] = vy.z; ys[r][k+3] = vy.w;
    }
    __syncthreads();

    const int tx = tid & 7, ty = tid >> 3;
    const int r0 = ty * 8, c0 = tx * 8;

    float acc[8][8];
    #pragma unroll
    for (int a = 0; a < 8; a++)
        #pragma unroll
        for (int b = 0; b < 8; b++) acc[a][b] = 0.f;

    #pragma unroll 4
    for (int k = 0; k < DD; k++) {
        float ra[8], rb[8];
        #pragma unroll
        for (int a = 0; a < 8; a++) ra[a] = xs[r0 + a][k];
        #pragma unroll
        for (int b = 0; b < 8; b++) rb[b] = ys[c0 + b][k];
        #pragma unroll
        for (int a = 0; a < 8; a++)
            #pragma unroll
            for (int b = 0; b < 8; b++) acc[a][b] = fmaf(ra[a], rb[b], acc[a][b]);
    }

    float nyv[8];
    #pragma unroll
    for (int b = 0; b < 8; b++) nyv[b] = g_ny[J0 + c0 + b];

    #pragma unroll
    for (int a = 0; a < 8; a++) {
        const int i = I0 + r0 + a;
        float nx = g_nx[i];
        #pragma unroll
        for (int b2 = 0; b2 < 4; b2++) {
            float s0 = nx + nyv[2*b2]   - 2.0f * acc[a][2*b2];
            float s1 = nx + nyv[2*b2+1] - 2.0f * acc[a][2*b2+1];
            float e0 = sqrtf(fmaxf(s0, 1e-12f));
            float e1 = sqrtf(fmaxf(s1, 1e-12f));
            const int lane = tx * 4 + b2;          // lane owning these 2 cols
            const int ss = i + lane;               // diagonal step index
            g_costd[((size_t)w * TSTEPS + ss) * 32 + lane] = __floats2half2_rn(e0, e1);
        }
    }

    if (w == 0 && I0 == 0 && tid == 0) {
        float sq = g_nx[0] + g_ny[0] - 2.0f * acc[0][0];   // tid0 owns (0,0)
        g_c00 = sqrtf(fmaxf(sq, 1e-12f));
    }
}

// ---------------------------------------------------------------------------
// Persistent DTW (round-11 dataflow; costs chunk-staged in registers):
// 64 strips x 1 warp; lane owns 2 adjacent columns; at step ss computes row
// r = ss - lane. Inner 32-step loop has ZERO loads — the chunk's 32 half2
// costs live in a double-buffered register file, refilled after each chunk
// (32 coalesced LDGs with a full chunk of latency slack).
// ---------------------------------------------------------------------------
__global__ void __launch_bounds__(32, 1) dtw_kernel(float* __restrict__ out) {
    const int w = blockIdx.x;
    const int lane = threadIdx.x;
    const __half2* cptr = g_costd + (size_t)w * TSTEPS * 32;

    // state: v1c0/v1c1 = D[prev row][c0/c1]; v2c1 = D[prev-1 row][c1]
    float v1c0 = BIGF, v1c1 = BIGF, v2c1 = BIGF;
    float prev0 = BIGF;                       // lane0: D[r-1][base-1]
    if (w == 0 && lane == 0)
        prev0 = -g_c00;                       // virtual corner seed

    float* bndW = g_bnd + (size_t)w * NN;
    const volatile float* bndp = g_bnd + (size_t)(w > 0 ? w - 1 : 0) * NN;
    const volatile int* vflag = (const volatile int*)&g_flag[w > 0 ? w - 1 : 0];
    int* flagW = &g_flag[w];

    // cost chunk double-buffer: 32 half2 each (current / next chunk)
    __half2 cpC[32], cpN[32];
    #pragma unroll
    for (int k = 0; k < 32; k++) cpC[k] = cptr[(size_t)k * 32 + lane];
    #pragma unroll
    for (int k = 0; k < 32; k++) cpN[k] = cptr[(size_t)(32 + k) * 32 + lane];

    for (int cs = 0; cs < TSTEPS; cs += 32) {
        // chunk poll + cooperative boundary load (uniform branch, 1/32 steps)
        float bval = BIGF;
        if (w > 0 && cs < NN) {
            while (*vflag < cs + 32) { }
            bval = bndp[cs + lane];
        }

        #pragma unroll
        for (int k = 0; k < 32; k++) {
            const int ss = cs + k;
            const int r = ss - lane;

            float lfs = __shfl_up_sync(FULLM, v1c1, 1);
            float dgs = __shfl_up_sync(FULLM, v2c1, 1);
            float bb  = __shfl_sync(FULLM, bval, k);

            const bool l0 = (lane == 0);
            float lfv = l0 ? bb : lfs;
            float dgv = l0 ? prev0 : dgs;
            prev0 = bb;

            float2 cc = __half22float2(cpC[k]);

            float n0 = fminf(fminf(fmaf(2.f, cc.x, dgv), v1c0 + cc.x), lfv + cc.x);
            float n1 = fminf(fminf(fmaf(2.f, cc.y, v1c0), v1c1 + cc.y), n0 + cc.y);

            const bool act = ((unsigned)r < NN);
            v2c1 = act ? v1c1 : v2c1;
            v1c0 = act ? n0 : v1c0;
            v1c1 = act ? n1 : v1c1;

            // boundary store (lane31 only, in-range) — predicated, no branch
            int rcl = r < 0 ? 0 : (r > NN - 1 ? NN - 1 : r);
            st_pred(bndW + rcl, n1, (int)(act && lane == 31));
        }

        // rotate buffers; refill cpN with chunk cs+64 (a full chunk of slack)
        #pragma unroll
        for (int k = 0; k < 32; k++) cpC[k] = cpN[k];
        if (cs + 64 < TSTEPS) {
            const size_t base = (size_t)(cs + 64) * 32 + lane;
            #pragma unroll
            for (int k = 0; k < 32; k++)
                cpN[k] = cptr[base + (size_t)k * 32];
        }

        // publish: flag = cs+1 (lane31 has completed rows 0..cs)
        if (lane == 31) {
            __threadfence();
            atomicExch(flagW, cs + 1);
        }
    }

    if (w == NWARP - 1 && lane == 31)
        out[0] = v1c1;          // D[4095][4095]
}

// ---------------------------------------------------------------------------
extern "C" void kernel_launch(void* const* d_in, const int* in_sizes, int n_in,
                              void* d_out, int out_size) {
    const float* x = (const float*)d_in[0];
    const float* y = (const float*)d_in[1];
    float* out = (float*)d_out;

    reset_kernel<<<1, 64>>>();
    norms_kernel<<<(2 * NN + 511) / 512, 512>>>(x, y);
    cost_kernel<<<dim3(NN / 64, NN / 64), 64>>>(x, y);
    dtw_kernel<<<NWARP, 32>>>(out);
}